// round 5
// baseline (speedup 1.0000x reference)
#include <cuda_runtime.h>
#include <math.h>

// ---------------- problem constants ----------------
#define NTOT  12288          // H*W*3
#define BATCH 64
#define KC    4096           // K per k-split chunk
#define NKC   3              // number of k-splits (3*4096 = 12288)
#define JT    128            // output columns per block
#define KB    32             // k per smem stage
#define OW    66             // obs smem row stride (pad: 2-way max bank conflict, 8B aligned)

// k-split partial results: [NKC][BATCH][NTOT]  (~9.4 MB static scratch)
__device__ __align__(16) float g_part[NKC * BATCH * NTOT];

#define FMA2(acc, a, b) \
    asm("fma.rn.f32x2 %0, %1, %2, %0;" : "+l"(acc) : "l"(a), "l"(b))

// ================= Kernel A: phi partial GEMM =================
// out-tile 64(M) x 128(N) per block, k-chunk 4096, FFMA2 (2 rows packed per 64-bit lane)
__global__ __launch_bounds__(256, 2)
void gemm_kernel(const float* __restrict__ obs, const float* __restrict__ w)
{
    extern __shared__ float sm[];
    float* sW = sm;                 // [2][KB][JT]
    float* sO = sm + 2 * KB * JT;   // [2][KB][OW] (rows 0..63 used)

    const int tid = threadIdx.x;
    const int j0  = blockIdx.x * JT;
    const int k0  = blockIdx.y * KC;

    // loader mapping
    const int kkL  = tid >> 5;   // 0..7 : w row within stage (stride 8)
    const int jjL  = tid & 31;   // w column-group (float4)
    const int kkO  = tid & 31;   // obs k within stage
    const int rowO = tid >> 5;   // obs row base (stride 8)

    // compute mapping
    const int rg = tid >> 5;     // row group: rows 8*rg .. 8*rg+7 (4 packed pairs)
    const int jj = tid & 31;     // column group: cols j0+4*jj .. +3

    const float* wbase = w   + (size_t)k0 * NTOT + j0 + jjL * 4;
    const float* obase = obs + (size_t)rowO * NTOT + k0 + kkO;

    float4 wr[4];
    float  orr[8];

    // prefetch stage 0
    {
        const float* wp = wbase + (size_t)kkL * NTOT;
        #pragma unroll
        for (int i = 0; i < 4; ++i)
            wr[i] = *(const float4*)(wp + (size_t)(8 * i) * NTOT);
        #pragma unroll
        for (int r = 0; r < 8; ++r)
            orr[r] = obase[(size_t)(8 * r) * NTOT];
    }

    unsigned long long acc[4][4];
    #pragma unroll
    for (int m = 0; m < 4; ++m)
        #pragma unroll
        for (int c = 0; c < 4; ++c) acc[m][c] = 0ULL;

    const int NIT = KC / KB;   // 128 stages
    for (int it = 0; it < NIT; ++it) {
        const int buf = it & 1;
        float* sWb = sW + buf * (KB * JT);
        float* sOb = sO + buf * (KB * OW);

        // commit prefetched stage to smem
        #pragma unroll
        for (int i = 0; i < 4; ++i)
            *(float4*)(sWb + (kkL + 8 * i) * JT + jjL * 4) = wr[i];
        #pragma unroll
        for (int r = 0; r < 8; ++r)
            sOb[kkO * OW + rowO + 8 * r] = orr[r];

        // prefetch next stage (latency overlapped with compute below)
        if (it + 1 < NIT) {
            const float* wp = wbase + (size_t)((it + 1) * KB + kkL) * NTOT;
            #pragma unroll
            for (int i = 0; i < 4; ++i)
                wr[i] = *(const float4*)(wp + (size_t)(8 * i) * NTOT);
            const float* op = obase + (it + 1) * KB;
            #pragma unroll
            for (int r = 0; r < 8; ++r)
                orr[r] = op[(size_t)(8 * r) * NTOT];
        }

        __syncthreads();   // one barrier per stage (ping-pong buffers)

        #pragma unroll
        for (int kk = 0; kk < KB; ++kk) {
            const float4 wv = *(const float4*)(sWb + kk * JT + jj * 4);
            unsigned long long wd0, wd1, wd2, wd3;
            asm("mov.b64 %0, {%1, %1};" : "=l"(wd0) : "f"(wv.x));
            asm("mov.b64 %0, {%1, %1};" : "=l"(wd1) : "f"(wv.y));
            asm("mov.b64 %0, {%1, %1};" : "=l"(wd2) : "f"(wv.z));
            asm("mov.b64 %0, {%1, %1};" : "=l"(wd3) : "f"(wv.w));
            const float* ob = sOb + kk * OW + 8 * rg;   // broadcast within warp
            unsigned long long a0 = *(const unsigned long long*)(ob + 0);
            unsigned long long a1 = *(const unsigned long long*)(ob + 2);
            unsigned long long a2 = *(const unsigned long long*)(ob + 4);
            unsigned long long a3 = *(const unsigned long long*)(ob + 6);
            FMA2(acc[0][0], a0, wd0); FMA2(acc[0][1], a0, wd1);
            FMA2(acc[0][2], a0, wd2); FMA2(acc[0][3], a0, wd3);
            FMA2(acc[1][0], a1, wd0); FMA2(acc[1][1], a1, wd1);
            FMA2(acc[1][2], a1, wd2); FMA2(acc[1][3], a1, wd3);
            FMA2(acc[2][0], a2, wd0); FMA2(acc[2][1], a2, wd1);
            FMA2(acc[2][2], a2, wd2); FMA2(acc[2][3], a2, wd3);
            FMA2(acc[3][0], a3, wd0); FMA2(acc[3][1], a3, wd1);
            FMA2(acc[3][2], a3, wd2); FMA2(acc[3][3], a3, wd3);
        }
    }

    // write partials
    float* outp = g_part + (size_t)blockIdx.y * (BATCH * NTOT);
    #pragma unroll
    for (int m = 0; m < 4; ++m) {
        float lo[4], hi[4];
        #pragma unroll
        for (int c = 0; c < 4; ++c)
            asm("mov.b64 {%0, %1}, %2;" : "=f"(lo[c]), "=f"(hi[c]) : "l"(acc[m][c]));
        const int row = 8 * rg + 2 * m;
        float4 v0 = make_float4(lo[0], lo[1], lo[2], lo[3]);
        float4 v1 = make_float4(hi[0], hi[1], hi[2], hi[3]);
        *(float4*)(outp + (size_t)row       * NTOT + j0 + jj * 4) = v0;
        *(float4*)(outp + (size_t)(row + 1) * NTOT + j0 + jj * 4) = v1;
    }
}

// ================= Kernel B: combine + softmax + VIN + head =================
// One block per batch element. 512 threads.
// shared layout (floats):
//   sC[4*4096] | sP[4096] | sRin[4096] | sRout[4096] | sVa[4356] | sVb[4356]
//   | sRed[16] | sPatch[36] | sH[16] | sIdx(20 ints)
#define OFF_C     0
#define OFF_P     16384
#define OFF_RIN   20480
#define OFF_ROUT  24576
#define OFF_VA    28672
#define OFF_VB    33028
#define OFF_RED   37384
#define OFF_PATCH 37400
#define OFF_H     37436
#define OFF_IDX   37452
#define SMEMB_FLOATS 37472

__global__ __launch_bounds__(512, 1)
void vin_kernel(const float* __restrict__ obs,
                const float* __restrict__ bias,
                const float* __restrict__ w1, const float* __restrict__ b1,
                const float* __restrict__ w2, const float* __restrict__ b2,
                float* __restrict__ out)
{
    extern __shared__ float sm[];
    float* sC    = sm + OFF_C;
    float* sP    = sm + OFF_P;
    float* sRin  = sm + OFF_RIN;
    float* sRout = sm + OFF_ROUT;
    float* sVa   = sm + OFF_VA;
    float* sVb   = sm + OFF_VB;
    float* sRed  = sm + OFF_RED;
    float* sPatch= sm + OFF_PATCH;
    float* sH    = sm + OFF_H;
    int*   sIdx  = (int*)(sm + OFF_IDX);

    const int b    = blockIdx.x;
    const int tid  = threadIdx.x;
    const int lane = tid & 31;
    const int wid  = tid >> 5;

    const float* pA = g_part + (size_t)(0 * BATCH + b) * NTOT;
    const float* pB = g_part + (size_t)(1 * BATCH + b) * NTOT;
    const float* pC = g_part + (size_t)(2 * BATCH + b) * NTOT;

    // ---- combine partials + bias, split into channels ----
    for (int cell = tid; cell < 4096; cell += 512) {
        int j = cell * 3;
        sRin[cell]  = pA[j]     + pB[j]     + pC[j]     + bias[j];
        sRout[cell] = pA[j + 1] + pB[j + 1] + pC[j + 1] + bias[j + 1];
        sP[cell]    = pA[j + 2] + pB[j + 2] + pC[j + 2] + bias[j + 2];
    }
    for (int i = tid; i < 4356; i += 512) { sVa[i] = 0.f; sVb[i] = 0.f; }
    __syncthreads();

    // ---- softmax over sP (4096) ----
    float m = -INFINITY;
    #pragma unroll
    for (int r = 0; r < 8; ++r) m = fmaxf(m, sP[tid + 512 * r]);
    #pragma unroll
    for (int off = 16; off; off >>= 1)
        m = fmaxf(m, __shfl_xor_sync(0xffffffffu, m, off));
    if (lane == 0) sRed[wid] = m;
    __syncthreads();
    float gm = sRed[0];
    #pragma unroll
    for (int i = 1; i < 16; ++i) gm = fmaxf(gm, sRed[i]);
    __syncthreads();            // protect sRed before reuse
    float s = 0.f;
    #pragma unroll
    for (int r = 0; r < 8; ++r) {
        int c = tid + 512 * r;
        float e = expf(sP[c] - gm);
        sP[c] = e; s += e;
    }
    #pragma unroll
    for (int off = 16; off; off >>= 1)
        s += __shfl_xor_sync(0xffffffffu, s, off);
    if (lane == 0) sRed[wid] = s;
    __syncthreads();
    float tot = 0.f;
    #pragma unroll
    for (int i = 0; i < 16; ++i) tot += sRed[i];
    float inv = 1.0f / tot;
    #pragma unroll
    for (int r = 0; r < 8; ++r) sP[tid + 512 * r] *= inv;

    // ---- per-direction constants: c = rin_sh - rout * (rin_sh != 0) ----
    for (int cell = tid; cell < 4096; cell += 512) {
        int h = cell >> 6, w_ = cell & 63;
        float rc = sRout[cell];
        float cu = 0.f, cd = 0.f, cl = 0.f, cr = 0.f;
        if (h > 0)   { float rn = sRin[cell - 64]; cu = rn - (rn != 0.f ? rc : 0.f); }
        if (h < 63)  { float rn = sRin[cell + 64]; cd = rn - (rn != 0.f ? rc : 0.f); }
        if (w_ > 0)  { float rn = sRin[cell - 1];  cl = rn - (rn != 0.f ? rc : 0.f); }
        if (w_ < 63) { float rn = sRin[cell + 1];  cr = rn - (rn != 0.f ? rc : 0.f); }
        sC[cell] = cu; sC[4096 + cell] = cd; sC[8192 + cell] = cl; sC[12288 + cell] = cr;
    }
    __syncthreads();   // sP normalization + sC complete

    // ---- K=64 value-iteration sweeps on padded 66x66 ping-pong V ----
    float pr[8], c0[8], c1[8], c2[8], c3[8];
    int   px[8];
    #pragma unroll
    for (int r = 0; r < 8; ++r) {
        int cell = tid + 512 * r;
        int h = cell >> 6, w_ = cell & 63;
        px[r] = (h + 1) * 66 + (w_ + 1);
        pr[r] = sP[cell];
        c0[r] = sC[cell];          c1[r] = sC[4096 + cell];
        c2[r] = sC[8192 + cell];   c3[r] = sC[12288 + cell];
    }
    float* cur = sVa;
    float* nxt = sVb;
    for (int itv = 0; itv < 64; ++itv) {
        #pragma unroll
        for (int r = 0; r < 8; ++r) {
            int pi = px[r];
            float nv = fmaf(pr[r], cur[pi - 66], c0[r]);            // up
            nv = fmaxf(nv, fmaf(pr[r], cur[pi + 66], c1[r]));       // down
            nv = fmaxf(nv, fmaf(pr[r], cur[pi - 1],  c2[r]));       // left
            nv = fmaxf(nv, fmaf(pr[r], cur[pi + 1],  c3[r]));       // right
            nxt[pi] = fmaxf(cur[pi], nv);
        }
        __syncthreads();
        float* t = cur; cur = nxt; nxt = t;
    }
    // final V is in `cur` (64 swaps -> sVa)

    // ---- argmax of obs channel 1 (first-max semantics) ----
    const float* ob = obs + (size_t)b * NTOT;
    float bv = -INFINITY; int bi = 0;
    #pragma unroll
    for (int r = 0; r < 8; ++r) {
        int cell = tid + 512 * r;
        float v = ob[cell * 3 + 1];
        if (v > bv) { bv = v; bi = cell; }
    }
    #pragma unroll
    for (int off = 16; off; off >>= 1) {
        float ov = __shfl_down_sync(0xffffffffu, bv, off);
        int   oi = __shfl_down_sync(0xffffffffu, bi, off);
        if (ov > bv || (ov == bv && oi < bi)) { bv = ov; bi = oi; }
    }
    if (lane == 0) { sRed[wid] = bv; sIdx[wid] = bi; }
    __syncthreads();
    if (tid == 0) {
        float bb = sRed[0]; int ii = sIdx[0];
        for (int i = 1; i < 16; ++i)
            if (sRed[i] > bb || (sRed[i] == bb && sIdx[i] < ii)) { bb = sRed[i]; ii = sIdx[i]; }
        sIdx[16] = ii;
    }
    __syncthreads();
    const int am  = sIdx[16];
    const int pi_ = am >> 6, pj_ = am & 63;

    // ---- 3x3x4 patch around agent, channels 0-2 from obs, 3 from V ----
    if (tid < 36) {
        int di = tid / 12, rem = tid % 12;
        int dj = rem >> 2, ch = rem & 3;
        float v;
        if (ch == 3) {
            v = cur[(pi_ + di) * 66 + (pj_ + dj)];   // padded V
        } else {
            int hh = pi_ + di - 1, ww = pj_ + dj - 1;
            v = (hh >= 0 && hh < 64 && ww >= 0 && ww < 64)
                    ? ob[(hh * 64 + ww) * 3 + ch] : 0.f;
        }
        sPatch[tid] = v;
    }
    __syncthreads();
    if (tid < 16) {
        float a = b1[tid];
        #pragma unroll
        for (int i = 0; i < 36; ++i) a = fmaf(sPatch[i], w1[i * 16 + tid], a);
        sH[tid] = fmaxf(a, 0.f);
    }
    __syncthreads();
    if (tid < 4) {
        float a = b2[tid];
        #pragma unroll
        for (int o = 0; o < 16; ++o) a = fmaf(sH[o], w2[o * 4 + tid], a);
        out[b * 4 + tid] = a;
    }
}

// ================= launcher =================
extern "C" void kernel_launch(void* const* d_in, const int* in_sizes, int n_in,
                              void* d_out, int out_size)
{
    const float* obs  = (const float*)d_in[0];
    const float* phiw = (const float*)d_in[1];
    const float* phib = (const float*)d_in[2];
    const float* w1   = (const float*)d_in[3];
    const float* b1   = (const float*)d_in[4];
    const float* w2   = (const float*)d_in[5];
    const float* b2   = (const float*)d_in[6];
    float* out = (float*)d_out;

    const int smemA = (2 * KB * JT + 2 * KB * OW) * (int)sizeof(float);   // 49664 B
    const int smemB = SMEMB_FLOATS * (int)sizeof(float);                  // 149888 B

    cudaFuncSetAttribute(gemm_kernel, cudaFuncAttributeMaxDynamicSharedMemorySize, smemA);
    cudaFuncSetAttribute(vin_kernel,  cudaFuncAttributeMaxDynamicSharedMemorySize, smemB);

    gemm_kernel<<<dim3(96, NKC), 256, smemA>>>(obs, phiw);
    vin_kernel<<<BATCH, 512, smemB>>>(obs, phib, w1, b1, w2, b2, out);
}

// round 6
// speedup vs baseline: 1.0441x; 1.0441x over previous
#include <cuda_runtime.h>
#include <math.h>

// ---------------- problem constants ----------------
#define NTOT  12288          // H*W*3
#define BATCH 64
#define KC    4096           // K per k-split chunk
#define NKC   3              // number of k-splits (3*4096 = 12288)
#define JT    128            // output columns per block
#define KB    32             // k per smem stage
#define OW    66             // obs smem row stride (pad: 2-way max bank conflict, 8B aligned)

// k-split partial results: [NKC][BATCH][NTOT]  (~9.4 MB static scratch)
__device__ __align__(16) float g_part[NKC * BATCH * NTOT];

#define FMA2(acc, a, b) \
    asm("fma.rn.f32x2 %0, %1, %2, %0;" : "+l"(acc) : "l"(a), "l"(b))

// ================= Kernel A: phi partial GEMM =================
// out-tile 64(M) x 128(N) per block, k-chunk 4096, FFMA2 (2 rows packed per 64-bit lane)
__global__ __launch_bounds__(256, 2)
void gemm_kernel(const float* __restrict__ obs, const float* __restrict__ w)
{
    extern __shared__ float sm[];
    float* sW = sm;                 // [2][KB][JT]
    float* sO = sm + 2 * KB * JT;   // [2][KB][OW] (rows 0..63 used)

    const int tid = threadIdx.x;
    const int j0  = blockIdx.x * JT;
    const int k0  = blockIdx.y * KC;

    // loader mapping
    const int kkL  = tid >> 5;   // 0..7 : w row within stage (stride 8)
    const int jjL  = tid & 31;   // w column-group (float4)
    const int kkO  = tid & 31;   // obs k within stage
    const int rowO = tid >> 5;   // obs row base (stride 8)

    // compute mapping
    const int rg = tid >> 5;     // row group: rows 8*rg .. 8*rg+7 (4 packed pairs)
    const int jj = tid & 31;     // column group: cols j0+4*jj .. +3

    const float* wbase = w   + (size_t)k0 * NTOT + j0 + jjL * 4;
    const float* obase = obs + (size_t)rowO * NTOT + k0 + kkO;

    float4 wr[4];
    float  orr[8];

    // prefetch stage 0
    {
        const float* wp = wbase + (size_t)kkL * NTOT;
        #pragma unroll
        for (int i = 0; i < 4; ++i)
            wr[i] = *(const float4*)(wp + (size_t)(8 * i) * NTOT);
        #pragma unroll
        for (int r = 0; r < 8; ++r)
            orr[r] = obase[(size_t)(8 * r) * NTOT];
    }

    unsigned long long acc[4][4];
    #pragma unroll
    for (int m = 0; m < 4; ++m)
        #pragma unroll
        for (int c = 0; c < 4; ++c) acc[m][c] = 0ULL;

    const int NIT = KC / KB;   // 128 stages
    for (int it = 0; it < NIT; ++it) {
        const int buf = it & 1;
        float* sWb = sW + buf * (KB * JT);
        float* sOb = sO + buf * (KB * OW);

        // commit prefetched stage to smem
        #pragma unroll
        for (int i = 0; i < 4; ++i)
            *(float4*)(sWb + (kkL + 8 * i) * JT + jjL * 4) = wr[i];
        #pragma unroll
        for (int r = 0; r < 8; ++r)
            sOb[kkO * OW + rowO + 8 * r] = orr[r];

        // prefetch next stage (latency overlapped with compute below)
        if (it + 1 < NIT) {
            const float* wp = wbase + (size_t)((it + 1) * KB + kkL) * NTOT;
            #pragma unroll
            for (int i = 0; i < 4; ++i)
                wr[i] = *(const float4*)(wp + (size_t)(8 * i) * NTOT);
            const float* op = obase + (it + 1) * KB;
            #pragma unroll
            for (int r = 0; r < 8; ++r)
                orr[r] = op[(size_t)(8 * r) * NTOT];
        }

        __syncthreads();   // one barrier per stage (ping-pong buffers)

        #pragma unroll
        for (int kk = 0; kk < KB; ++kk) {
            const float4 wv = *(const float4*)(sWb + kk * JT + jj * 4);
            unsigned long long wd0, wd1, wd2, wd3;
            asm("mov.b64 %0, {%1, %1};" : "=l"(wd0) : "f"(wv.x));
            asm("mov.b64 %0, {%1, %1};" : "=l"(wd1) : "f"(wv.y));
            asm("mov.b64 %0, {%1, %1};" : "=l"(wd2) : "f"(wv.z));
            asm("mov.b64 %0, {%1, %1};" : "=l"(wd3) : "f"(wv.w));
            const float* ob = sOb + kk * OW + 8 * rg;   // broadcast within warp
            unsigned long long a0 = *(const unsigned long long*)(ob + 0);
            unsigned long long a1 = *(const unsigned long long*)(ob + 2);
            unsigned long long a2 = *(const unsigned long long*)(ob + 4);
            unsigned long long a3 = *(const unsigned long long*)(ob + 6);
            FMA2(acc[0][0], a0, wd0); FMA2(acc[0][1], a0, wd1);
            FMA2(acc[0][2], a0, wd2); FMA2(acc[0][3], a0, wd3);
            FMA2(acc[1][0], a1, wd0); FMA2(acc[1][1], a1, wd1);
            FMA2(acc[1][2], a1, wd2); FMA2(acc[1][3], a1, wd3);
            FMA2(acc[2][0], a2, wd0); FMA2(acc[2][1], a2, wd1);
            FMA2(acc[2][2], a2, wd2); FMA2(acc[2][3], a2, wd3);
            FMA2(acc[3][0], a3, wd0); FMA2(acc[3][1], a3, wd1);
            FMA2(acc[3][2], a3, wd2); FMA2(acc[3][3], a3, wd3);
        }
    }

    // write partials
    float* outp = g_part + (size_t)blockIdx.y * (BATCH * NTOT);
    #pragma unroll
    for (int m = 0; m < 4; ++m) {
        float lo[4], hi[4];
        #pragma unroll
        for (int c = 0; c < 4; ++c)
            asm("mov.b64 {%0, %1}, %2;" : "=f"(lo[c]), "=f"(hi[c]) : "l"(acc[m][c]));
        const int row = 8 * rg + 2 * m;
        float4 v0 = make_float4(lo[0], lo[1], lo[2], lo[3]);
        float4 v1 = make_float4(hi[0], hi[1], hi[2], hi[3]);
        *(float4*)(outp + (size_t)row       * NTOT + j0 + jj * 4) = v0;
        *(float4*)(outp + (size_t)(row + 1) * NTOT + j0 + jj * 4) = v1;
    }
}

// ================= Kernel B: combine + softmax + VIN + head =================
// One block per batch element. 512 threads.
// shared layout (floats):
//   sC[4*4096] | sP[4096] | sRin[4096] | sRout[4096] | sVa[4356] | sVb[4356]
//   | sRed[16] | sPatch[36] | sH[16] | sIdx(20 ints)
#define OFF_C     0
#define OFF_P     16384
#define OFF_RIN   20480
#define OFF_ROUT  24576
#define OFF_VA    28672
#define OFF_VB    33028
#define OFF_RED   37384
#define OFF_PATCH 37400
#define OFF_H     37436
#define OFF_IDX   37452
#define SMEMB_FLOATS 37472

__global__ __launch_bounds__(512, 1)
void vin_kernel(const float* __restrict__ obs,
                const float* __restrict__ bias,
                const float* __restrict__ w1, const float* __restrict__ b1,
                const float* __restrict__ w2, const float* __restrict__ b2,
                float* __restrict__ out)
{
    extern __shared__ float sm[];
    float* sC    = sm + OFF_C;
    float* sP    = sm + OFF_P;
    float* sRin  = sm + OFF_RIN;
    float* sRout = sm + OFF_ROUT;
    float* sVa   = sm + OFF_VA;
    float* sVb   = sm + OFF_VB;
    float* sRed  = sm + OFF_RED;
    float* sPatch= sm + OFF_PATCH;
    float* sH    = sm + OFF_H;
    int*   sIdx  = (int*)(sm + OFF_IDX);

    const int b    = blockIdx.x;
    const int tid  = threadIdx.x;
    const int lane = tid & 31;
    const int wid  = tid >> 5;

    const float* pA = g_part + (size_t)(0 * BATCH + b) * NTOT;
    const float* pB = g_part + (size_t)(1 * BATCH + b) * NTOT;
    const float* pC = g_part + (size_t)(2 * BATCH + b) * NTOT;

    // ---- combine partials + bias, split into channels ----
    for (int cell = tid; cell < 4096; cell += 512) {
        int j = cell * 3;
        sRin[cell]  = pA[j]     + pB[j]     + pC[j]     + bias[j];
        sRout[cell] = pA[j + 1] + pB[j + 1] + pC[j + 1] + bias[j + 1];
        sP[cell]    = pA[j + 2] + pB[j + 2] + pC[j + 2] + bias[j + 2];
    }
    for (int i = tid; i < 4356; i += 512) { sVa[i] = 0.f; sVb[i] = 0.f; }
    __syncthreads();

    // ---- softmax over sP (4096) ----
    float m = -INFINITY;
    #pragma unroll
    for (int r = 0; r < 8; ++r) m = fmaxf(m, sP[tid + 512 * r]);
    #pragma unroll
    for (int off = 16; off; off >>= 1)
        m = fmaxf(m, __shfl_xor_sync(0xffffffffu, m, off));
    if (lane == 0) sRed[wid] = m;
    __syncthreads();
    float gm = sRed[0];
    #pragma unroll
    for (int i = 1; i < 16; ++i) gm = fmaxf(gm, sRed[i]);
    __syncthreads();            // protect sRed before reuse
    float s = 0.f;
    #pragma unroll
    for (int r = 0; r < 8; ++r) {
        int c = tid + 512 * r;
        float e = expf(sP[c] - gm);
        sP[c] = e; s += e;
    }
    #pragma unroll
    for (int off = 16; off; off >>= 1)
        s += __shfl_xor_sync(0xffffffffu, s, off);
    if (lane == 0) sRed[wid] = s;
    __syncthreads();
    float tot = 0.f;
    #pragma unroll
    for (int i = 0; i < 16; ++i) tot += sRed[i];
    float inv = 1.0f / tot;
    #pragma unroll
    for (int r = 0; r < 8; ++r) sP[tid + 512 * r] *= inv;

    // ---- per-direction constants: c = rin_sh - rout * (rin_sh != 0) ----
    for (int cell = tid; cell < 4096; cell += 512) {
        int h = cell >> 6, w_ = cell & 63;
        float rc = sRout[cell];
        float cu = 0.f, cd = 0.f, cl = 0.f, cr = 0.f;
        if (h > 0)   { float rn = sRin[cell - 64]; cu = rn - (rn != 0.f ? rc : 0.f); }
        if (h < 63)  { float rn = sRin[cell + 64]; cd = rn - (rn != 0.f ? rc : 0.f); }
        if (w_ > 0)  { float rn = sRin[cell - 1];  cl = rn - (rn != 0.f ? rc : 0.f); }
        if (w_ < 63) { float rn = sRin[cell + 1];  cr = rn - (rn != 0.f ? rc : 0.f); }
        sC[cell] = cu; sC[4096 + cell] = cd; sC[8192 + cell] = cl; sC[12288 + cell] = cr;
    }
    __syncthreads();   // sP normalization + sC complete

    // ---- K=64 value-iteration sweeps on padded 66x66 ping-pong V ----
    float pr[8], c0[8], c1[8], c2[8], c3[8];
    int   px[8];
    #pragma unroll
    for (int r = 0; r < 8; ++r) {
        int cell = tid + 512 * r;
        int h = cell >> 6, w_ = cell & 63;
        px[r] = (h + 1) * 66 + (w_ + 1);
        pr[r] = sP[cell];
        c0[r] = sC[cell];          c1[r] = sC[4096 + cell];
        c2[r] = sC[8192 + cell];   c3[r] = sC[12288 + cell];
    }
    float* cur = sVa;
    float* nxt = sVb;
    for (int itv = 0; itv < 64; ++itv) {
        #pragma unroll
        for (int r = 0; r < 8; ++r) {
            int pi = px[r];
            float nv = fmaf(pr[r], cur[pi - 66], c0[r]);            // up
            nv = fmaxf(nv, fmaf(pr[r], cur[pi + 66], c1[r]));       // down
            nv = fmaxf(nv, fmaf(pr[r], cur[pi - 1],  c2[r]));       // left
            nv = fmaxf(nv, fmaf(pr[r], cur[pi + 1],  c3[r]));       // right
            nxt[pi] = fmaxf(cur[pi], nv);
        }
        __syncthreads();
        float* t = cur; cur = nxt; nxt = t;
    }
    // final V is in `cur` (64 swaps -> sVa)

    // ---- argmax of obs channel 1 (first-max semantics) ----
    const float* ob = obs + (size_t)b * NTOT;
    float bv = -INFINITY; int bi = 0;
    #pragma unroll
    for (int r = 0; r < 8; ++r) {
        int cell = tid + 512 * r;
        float v = ob[cell * 3 + 1];
        if (v > bv) { bv = v; bi = cell; }
    }
    #pragma unroll
    for (int off = 16; off; off >>= 1) {
        float ov = __shfl_down_sync(0xffffffffu, bv, off);
        int   oi = __shfl_down_sync(0xffffffffu, bi, off);
        if (ov > bv || (ov == bv && oi < bi)) { bv = ov; bi = oi; }
    }
    if (lane == 0) { sRed[wid] = bv; sIdx[wid] = bi; }
    __syncthreads();
    if (tid == 0) {
        float bb = sRed[0]; int ii = sIdx[0];
        for (int i = 1; i < 16; ++i)
            if (sRed[i] > bb || (sRed[i] == bb && sIdx[i] < ii)) { bb = sRed[i]; ii = sIdx[i]; }
        sIdx[16] = ii;
    }
    __syncthreads();
    const int am  = sIdx[16];
    const int pi_ = am >> 6, pj_ = am & 63;

    // ---- 3x3x4 patch around agent, channels 0-2 from obs, 3 from V ----
    if (tid < 36) {
        int di = tid / 12, rem = tid % 12;
        int dj = rem >> 2, ch = rem & 3;
        float v;
        if (ch == 3) {
            v = cur[(pi_ + di) * 66 + (pj_ + dj)];   // padded V
        } else {
            int hh = pi_ + di - 1, ww = pj_ + dj - 1;
            v = (hh >= 0 && hh < 64 && ww >= 0 && ww < 64)
                    ? ob[(hh * 64 + ww) * 3 + ch] : 0.f;
        }
        sPatch[tid] = v;
    }
    __syncthreads();
    if (tid < 16) {
        float a = b1[tid];
        #pragma unroll
        for (int i = 0; i < 36; ++i) a = fmaf(sPatch[i], w1[i * 16 + tid], a);
        sH[tid] = fmaxf(a, 0.f);
    }
    __syncthreads();
    if (tid < 4) {
        float a = b2[tid];
        #pragma unroll
        for (int o = 0; o < 16; ++o) a = fmaf(sH[o], w2[o * 4 + tid], a);
        out[b * 4 + tid] = a;
    }
}

// ================= launcher =================
extern "C" void kernel_launch(void* const* d_in, const int* in_sizes, int n_in,
                              void* d_out, int out_size)
{
    const float* obs  = (const float*)d_in[0];
    const float* phiw = (const float*)d_in[1];
    const float* phib = (const float*)d_in[2];
    const float* w1   = (const float*)d_in[3];
    const float* b1   = (const float*)d_in[4];
    const float* w2   = (const float*)d_in[5];
    const float* b2   = (const float*)d_in[6];
    float* out = (float*)d_out;

    const int smemA = (2 * KB * JT + 2 * KB * OW) * (int)sizeof(float);   // 49664 B
    const int smemB = SMEMB_FLOATS * (int)sizeof(float);                  // 149888 B

    cudaFuncSetAttribute(gemm_kernel, cudaFuncAttributeMaxDynamicSharedMemorySize, smemA);
    cudaFuncSetAttribute(vin_kernel,  cudaFuncAttributeMaxDynamicSharedMemorySize, smemB);

    gemm_kernel<<<dim3(96, NKC), 256, smemA>>>(obs, phiw);
    vin_kernel<<<BATCH, 512, smemB>>>(obs, phib, w1, b1, w2, b2, out);
}

// round 7
// speedup vs baseline: 1.0487x; 1.0045x over previous
#include <cuda_runtime.h>
#include <math.h>

// ---------------- problem constants ----------------
#define NTOT  12288          // H*W*3
#define BATCH 64
#define KC    4096           // K per k-split chunk
#define NKC   3              // number of k-splits (3*4096 = 12288)
#define JT    128            // output columns per block
#define KB    32             // k per smem stage
#define OW    66             // obs smem row stride (pad: 2-way max bank conflict, 8B aligned)

// k-split partial results: [NKC][BATCH][NTOT]  (~9.4 MB static scratch)
__device__ __align__(16) float g_part[NKC * BATCH * NTOT];

#define FMA2(acc, a, b) \
    asm("fma.rn.f32x2 %0, %1, %2, %0;" : "+l"(acc) : "l"(a), "l"(b))

// ================= Kernel A: phi partial GEMM =================
// out-tile 64(M) x 128(N) per block, k-chunk 4096, FFMA2 (2 rows packed per 64-bit lane)
__global__ __launch_bounds__(256, 2)
void gemm_kernel(const float* __restrict__ obs, const float* __restrict__ w)
{
    extern __shared__ float sm[];
    float* sW = sm;                 // [2][KB][JT]
    float* sO = sm + 2 * KB * JT;   // [2][KB][OW] (rows 0..63 used)

    const int tid = threadIdx.x;
    const int j0  = blockIdx.x * JT;
    const int k0  = blockIdx.y * KC;

    // loader mapping
    const int kkL  = tid >> 5;   // 0..7 : w row within stage (stride 8)
    const int jjL  = tid & 31;   // w column-group (float4)
    const int kkO  = tid & 31;   // obs k within stage
    const int rowO = tid >> 5;   // obs row base (stride 8)

    // compute mapping
    const int rg = tid >> 5;     // row group: rows 8*rg .. 8*rg+7 (4 packed pairs)
    const int jj = tid & 31;     // column group: cols j0+4*jj .. +3

    const float* wbase = w   + (size_t)k0 * NTOT + j0 + jjL * 4;
    const float* obase = obs + (size_t)rowO * NTOT + k0 + kkO;

    float4 wr[4];
    float  orr[8];

    // prefetch stage 0
    {
        const float* wp = wbase + (size_t)kkL * NTOT;
        #pragma unroll
        for (int i = 0; i < 4; ++i)
            wr[i] = *(const float4*)(wp + (size_t)(8 * i) * NTOT);
        #pragma unroll
        for (int r = 0; r < 8; ++r)
            orr[r] = obase[(size_t)(8 * r) * NTOT];
    }

    unsigned long long acc[4][4];
    #pragma unroll
    for (int m = 0; m < 4; ++m)
        #pragma unroll
        for (int c = 0; c < 4; ++c) acc[m][c] = 0ULL;

    const int NIT = KC / KB;   // 128 stages
    for (int it = 0; it < NIT; ++it) {
        const int buf = it & 1;
        float* sWb = sW + buf * (KB * JT);
        float* sOb = sO + buf * (KB * OW);

        // commit prefetched stage to smem
        #pragma unroll
        for (int i = 0; i < 4; ++i)
            *(float4*)(sWb + (kkL + 8 * i) * JT + jjL * 4) = wr[i];
        #pragma unroll
        for (int r = 0; r < 8; ++r)
            sOb[kkO * OW + rowO + 8 * r] = orr[r];

        // prefetch next stage (latency overlapped with compute below)
        if (it + 1 < NIT) {
            const float* wp = wbase + (size_t)((it + 1) * KB + kkL) * NTOT;
            #pragma unroll
            for (int i = 0; i < 4; ++i)
                wr[i] = *(const float4*)(wp + (size_t)(8 * i) * NTOT);
            const float* op = obase + (it + 1) * KB;
            #pragma unroll
            for (int r = 0; r < 8; ++r)
                orr[r] = op[(size_t)(8 * r) * NTOT];
        }

        __syncthreads();   // one barrier per stage (ping-pong buffers)

        #pragma unroll
        for (int kk = 0; kk < KB; ++kk) {
            const float4 wv = *(const float4*)(sWb + kk * JT + jj * 4);
            unsigned long long wd0, wd1, wd2, wd3;
            asm("mov.b64 %0, {%1, %1};" : "=l"(wd0) : "f"(wv.x));
            asm("mov.b64 %0, {%1, %1};" : "=l"(wd1) : "f"(wv.y));
            asm("mov.b64 %0, {%1, %1};" : "=l"(wd2) : "f"(wv.z));
            asm("mov.b64 %0, {%1, %1};" : "=l"(wd3) : "f"(wv.w));
            const float* ob = sOb + kk * OW + 8 * rg;   // broadcast within warp
            unsigned long long a0 = *(const unsigned long long*)(ob + 0);
            unsigned long long a1 = *(const unsigned long long*)(ob + 2);
            unsigned long long a2 = *(const unsigned long long*)(ob + 4);
            unsigned long long a3 = *(const unsigned long long*)(ob + 6);
            FMA2(acc[0][0], a0, wd0); FMA2(acc[0][1], a0, wd1);
            FMA2(acc[0][2], a0, wd2); FMA2(acc[0][3], a0, wd3);
            FMA2(acc[1][0], a1, wd0); FMA2(acc[1][1], a1, wd1);
            FMA2(acc[1][2], a1, wd2); FMA2(acc[1][3], a1, wd3);
            FMA2(acc[2][0], a2, wd0); FMA2(acc[2][1], a2, wd1);
            FMA2(acc[2][2], a2, wd2); FMA2(acc[2][3], a2, wd3);
            FMA2(acc[3][0], a3, wd0); FMA2(acc[3][1], a3, wd1);
            FMA2(acc[3][2], a3, wd2); FMA2(acc[3][3], a3, wd3);
        }
    }

    // write partials
    float* outp = g_part + (size_t)blockIdx.y * (BATCH * NTOT);
    #pragma unroll
    for (int m = 0; m < 4; ++m) {
        float lo[4], hi[4];
        #pragma unroll
        for (int c = 0; c < 4; ++c)
            asm("mov.b64 {%0, %1}, %2;" : "=f"(lo[c]), "=f"(hi[c]) : "l"(acc[m][c]));
        const int row = 8 * rg + 2 * m;
        float4 v0 = make_float4(lo[0], lo[1], lo[2], lo[3]);
        float4 v1 = make_float4(hi[0], hi[1], hi[2], hi[3]);
        *(float4*)(outp + (size_t)row       * NTOT + j0 + jj * 4) = v0;
        *(float4*)(outp + (size_t)(row + 1) * NTOT + j0 + jj * 4) = v1;
    }
}

// ================= Kernel B: combine + softmax + VIN + head =================
// One block per batch element. 512 threads.
// shared layout (floats):
//   sC[4*4096] | sP[4096] | sRin[4096] | sRout[4096] | sVa[4356] | sVb[4356]
//   | sRed[16] | sPatch[36] | sH[16] | sIdx(20 ints)
#define OFF_C     0
#define OFF_P     16384
#define OFF_RIN   20480
#define OFF_ROUT  24576
#define OFF_VA    28672
#define OFF_VB    33028
#define OFF_RED   37384
#define OFF_PATCH 37400
#define OFF_H     37436
#define OFF_IDX   37452
#define SMEMB_FLOATS 37472

__global__ __launch_bounds__(512, 1)
void vin_kernel(const float* __restrict__ obs,
                const float* __restrict__ bias,
                const float* __restrict__ w1, const float* __restrict__ b1,
                const float* __restrict__ w2, const float* __restrict__ b2,
                float* __restrict__ out)
{
    extern __shared__ float sm[];
    float* sC    = sm + OFF_C;
    float* sP    = sm + OFF_P;
    float* sRin  = sm + OFF_RIN;
    float* sRout = sm + OFF_ROUT;
    float* sVa   = sm + OFF_VA;
    float* sVb   = sm + OFF_VB;
    float* sRed  = sm + OFF_RED;
    float* sPatch= sm + OFF_PATCH;
    float* sH    = sm + OFF_H;
    int*   sIdx  = (int*)(sm + OFF_IDX);

    const int b    = blockIdx.x;
    const int tid  = threadIdx.x;
    const int lane = tid & 31;
    const int wid  = tid >> 5;

    const float* pA = g_part + (size_t)(0 * BATCH + b) * NTOT;
    const float* pB = g_part + (size_t)(1 * BATCH + b) * NTOT;
    const float* pC = g_part + (size_t)(2 * BATCH + b) * NTOT;

    // ---- combine partials + bias, split into channels ----
    for (int cell = tid; cell < 4096; cell += 512) {
        int j = cell * 3;
        sRin[cell]  = pA[j]     + pB[j]     + pC[j]     + bias[j];
        sRout[cell] = pA[j + 1] + pB[j + 1] + pC[j + 1] + bias[j + 1];
        sP[cell]    = pA[j + 2] + pB[j + 2] + pC[j + 2] + bias[j + 2];
    }
    for (int i = tid; i < 4356; i += 512) { sVa[i] = 0.f; sVb[i] = 0.f; }
    __syncthreads();

    // ---- softmax over sP (4096) ----
    float m = -INFINITY;
    #pragma unroll
    for (int r = 0; r < 8; ++r) m = fmaxf(m, sP[tid + 512 * r]);
    #pragma unroll
    for (int off = 16; off; off >>= 1)
        m = fmaxf(m, __shfl_xor_sync(0xffffffffu, m, off));
    if (lane == 0) sRed[wid] = m;
    __syncthreads();
    float gm = sRed[0];
    #pragma unroll
    for (int i = 1; i < 16; ++i) gm = fmaxf(gm, sRed[i]);
    __syncthreads();            // protect sRed before reuse
    float s = 0.f;
    #pragma unroll
    for (int r = 0; r < 8; ++r) {
        int c = tid + 512 * r;
        float e = expf(sP[c] - gm);
        sP[c] = e; s += e;
    }
    #pragma unroll
    for (int off = 16; off; off >>= 1)
        s += __shfl_xor_sync(0xffffffffu, s, off);
    if (lane == 0) sRed[wid] = s;
    __syncthreads();
    float tot = 0.f;
    #pragma unroll
    for (int i = 0; i < 16; ++i) tot += sRed[i];
    float inv = 1.0f / tot;
    #pragma unroll
    for (int r = 0; r < 8; ++r) sP[tid + 512 * r] *= inv;

    // ---- per-direction constants: c = rin_sh - rout * (rin_sh != 0) ----
    for (int cell = tid; cell < 4096; cell += 512) {
        int h = cell >> 6, w_ = cell & 63;
        float rc = sRout[cell];
        float cu = 0.f, cd = 0.f, cl = 0.f, cr = 0.f;
        if (h > 0)   { float rn = sRin[cell - 64]; cu = rn - (rn != 0.f ? rc : 0.f); }
        if (h < 63)  { float rn = sRin[cell + 64]; cd = rn - (rn != 0.f ? rc : 0.f); }
        if (w_ > 0)  { float rn = sRin[cell - 1];  cl = rn - (rn != 0.f ? rc : 0.f); }
        if (w_ < 63) { float rn = sRin[cell + 1];  cr = rn - (rn != 0.f ? rc : 0.f); }
        sC[cell] = cu; sC[4096 + cell] = cd; sC[8192 + cell] = cl; sC[12288 + cell] = cr;
    }
    __syncthreads();   // sP normalization + sC complete

    // ---- K=64 value-iteration sweeps on padded 66x66 ping-pong V ----
    float pr[8], c0[8], c1[8], c2[8], c3[8];
    int   px[8];
    #pragma unroll
    for (int r = 0; r < 8; ++r) {
        int cell = tid + 512 * r;
        int h = cell >> 6, w_ = cell & 63;
        px[r] = (h + 1) * 66 + (w_ + 1);
        pr[r] = sP[cell];
        c0[r] = sC[cell];          c1[r] = sC[4096 + cell];
        c2[r] = sC[8192 + cell];   c3[r] = sC[12288 + cell];
    }
    float* cur = sVa;
    float* nxt = sVb;
    for (int itv = 0; itv < 64; ++itv) {
        #pragma unroll
        for (int r = 0; r < 8; ++r) {
            int pi = px[r];
            float nv = fmaf(pr[r], cur[pi - 66], c0[r]);            // up
            nv = fmaxf(nv, fmaf(pr[r], cur[pi + 66], c1[r]));       // down
            nv = fmaxf(nv, fmaf(pr[r], cur[pi - 1],  c2[r]));       // left
            nv = fmaxf(nv, fmaf(pr[r], cur[pi + 1],  c3[r]));       // right
            nxt[pi] = fmaxf(cur[pi], nv);
        }
        __syncthreads();
        float* t = cur; cur = nxt; nxt = t;
    }
    // final V is in `cur` (64 swaps -> sVa)

    // ---- argmax of obs channel 1 (first-max semantics) ----
    const float* ob = obs + (size_t)b * NTOT;
    float bv = -INFINITY; int bi = 0;
    #pragma unroll
    for (int r = 0; r < 8; ++r) {
        int cell = tid + 512 * r;
        float v = ob[cell * 3 + 1];
        if (v > bv) { bv = v; bi = cell; }
    }
    #pragma unroll
    for (int off = 16; off; off >>= 1) {
        float ov = __shfl_down_sync(0xffffffffu, bv, off);
        int   oi = __shfl_down_sync(0xffffffffu, bi, off);
        if (ov > bv || (ov == bv && oi < bi)) { bv = ov; bi = oi; }
    }
    if (lane == 0) { sRed[wid] = bv; sIdx[wid] = bi; }
    __syncthreads();
    if (tid == 0) {
        float bb = sRed[0]; int ii = sIdx[0];
        for (int i = 1; i < 16; ++i)
            if (sRed[i] > bb || (sRed[i] == bb && sIdx[i] < ii)) { bb = sRed[i]; ii = sIdx[i]; }
        sIdx[16] = ii;
    }
    __syncthreads();
    const int am  = sIdx[16];
    const int pi_ = am >> 6, pj_ = am & 63;

    // ---- 3x3x4 patch around agent, channels 0-2 from obs, 3 from V ----
    if (tid < 36) {
        int di = tid / 12, rem = tid % 12;
        int dj = rem >> 2, ch = rem & 3;
        float v;
        if (ch == 3) {
            v = cur[(pi_ + di) * 66 + (pj_ + dj)];   // padded V
        } else {
            int hh = pi_ + di - 1, ww = pj_ + dj - 1;
            v = (hh >= 0 && hh < 64 && ww >= 0 && ww < 64)
                    ? ob[(hh * 64 + ww) * 3 + ch] : 0.f;
        }
        sPatch[tid] = v;
    }
    __syncthreads();
    if (tid < 16) {
        float a = b1[tid];
        #pragma unroll
        for (int i = 0; i < 36; ++i) a = fmaf(sPatch[i], w1[i * 16 + tid], a);
        sH[tid] = fmaxf(a, 0.f);
    }
    __syncthreads();
    if (tid < 4) {
        float a = b2[tid];
        #pragma unroll
        for (int o = 0; o < 16; ++o) a = fmaf(sH[o], w2[o * 4 + tid], a);
        out[b * 4 + tid] = a;
    }
}

// ================= launcher =================
extern "C" void kernel_launch(void* const* d_in, const int* in_sizes, int n_in,
                              void* d_out, int out_size)
{
    const float* obs  = (const float*)d_in[0];
    const float* phiw = (const float*)d_in[1];
    const float* phib = (const float*)d_in[2];
    const float* w1   = (const float*)d_in[3];
    const float* b1   = (const float*)d_in[4];
    const float* w2   = (const float*)d_in[5];
    const float* b2   = (const float*)d_in[6];
    float* out = (float*)d_out;

    const int smemA = (2 * KB * JT + 2 * KB * OW) * (int)sizeof(float);   // 49664 B
    const int smemB = SMEMB_FLOATS * (int)sizeof(float);                  // 149888 B

    cudaFuncSetAttribute(gemm_kernel, cudaFuncAttributeMaxDynamicSharedMemorySize, smemA);
    cudaFuncSetAttribute(vin_kernel,  cudaFuncAttributeMaxDynamicSharedMemorySize, smemB);

    gemm_kernel<<<dim3(96, NKC), 256, smemA>>>(obs, phiw);
    vin_kernel<<<BATCH, 512, smemB>>>(obs, phib, w1, b1, w2, b2, out);
}

// round 9
// speedup vs baseline: 1.8860x; 1.7984x over previous
#include <cuda_runtime.h>
#include <math.h>

// ---------------- problem constants ----------------
#define NTOT   12288         // H*W*3
#define BATCH  64
#define KCH    4096          // K per k-split slice
#define NKC    3
#define NTILE  128           // output cols per CTA
#define KSTAGE 32            // k per smem stage
#define NSTAGE (KCH / KSTAGE)   // 128

// k-split partials: [NKC][BATCH][NTOT]  (~9.4 MB scratch)
__device__ __align__(16) float g_part[NKC * BATCH * NTOT];

// ---------------- smem layout (bytes) ----------------
// A planes: [2 buf][64 m][80 B]  (32 bf16 + pad)   per buf-plane 5120
// B planes: [2 buf][32 k][272 B] (128 bf16 + pad)  per buf-plane 8704
#define A_STRIDE 80
#define B_STRIDE 272
#define OFF_AH  0
#define OFF_AL  10240
#define OFF_BH  20480
#define OFF_BL  37888
#define SMEMA_TOTAL 55296

__device__ __forceinline__ unsigned smem_u32(const void* p) {
    unsigned a;
    asm("{ .reg .u64 t; cvta.to.shared.u64 t, %1; cvt.u32.u64 %0, t; }" : "=r"(a) : "l"(p));
    return a;
}

// bf16 hi/lo split: word = (bf16(a) low 16) | (bf16(b) high 16)
__device__ __forceinline__ unsigned packbf(float a, float b) {
    unsigned r;
    asm("cvt.rn.bf16x2.f32 %0, %1, %2;" : "=r"(r) : "f"(b), "f"(a));
    return r;
}
__device__ __forceinline__ void hilo2(float a, float b, unsigned& h, unsigned& l) {
    h = packbf(a, b);
    float ha = __uint_as_float(h << 16);
    float hb = __uint_as_float(h & 0xffff0000u);
    l = packbf(a - ha, b - hb);
}

#define LDMX4(r0, r1, r2, r3, addr) \
    asm volatile("ldmatrix.sync.aligned.m8n8.x4.shared.b16 {%0,%1,%2,%3}, [%4];" \
                 : "=r"(r0), "=r"(r1), "=r"(r2), "=r"(r3) : "r"(addr))
#define LDMX4T(r0, r1, r2, r3, addr) \
    asm volatile("ldmatrix.sync.aligned.m8n8.x4.trans.shared.b16 {%0,%1,%2,%3}, [%4];" \
                 : "=r"(r0), "=r"(r1), "=r"(r2), "=r"(r3) : "r"(addr))
#define MMA16816(d, a, b) \
    asm volatile("mma.sync.aligned.m16n8k16.row.col.f32.bf16.bf16.f32 " \
                 "{%0,%1,%2,%3}, {%4,%5,%6,%7}, {%8,%9}, {%0,%1,%2,%3};" \
                 : "+f"((d)[0]), "+f"((d)[1]), "+f"((d)[2]), "+f"((d)[3]) \
                 : "r"((a)[0]), "r"((a)[1]), "r"((a)[2]), "r"((a)[3]), \
                   "r"((b)[0]), "r"((b)[1]))

// ================= Kernel A: mma.sync bf16 hi/lo GEMM =================
// C[64, n-tile 128] partial over k-chunk 4096. 8 warps = 2M x 4N, warp 32x32.
__global__ __launch_bounds__(256, 2)
void gemm_mma(const float* __restrict__ obs, const float* __restrict__ W)
{
    extern __shared__ char smem[];
    const unsigned sbase = smem_u32(smem);
    const int tid  = threadIdx.x;
    const int lane = tid & 31;
    const int wid  = tid >> 5;
    const int n0   = blockIdx.x * NTILE;
    const int k0   = blockIdx.y * KCH;

    const int wm = wid >> 2;          // 0..1 -> m base 32*wm
    const int wn = wid & 3;           // 0..3 -> n base 32*wn
    const int mbase = 32 * wm;
    const int nbase = 32 * wn;

    // ---- loader mappings ----
    const int am = tid >> 2;          // A: row m 0..63
    const int aq = tid & 3;           // A: k-octet 0..3 (8 k each)
    // B: warp w loads rows {w, w+8, w+16, w+24}, float4 at n = 4*lane

    // ---- ldmatrix address precompute ----
    // A (non-trans, 16x16): lane groups -> (m_off, k_off)
    const int a_mo = ((lane >> 3) & 1) * 8 + (lane & 7);
    const int a_ko = (lane >> 4) * 8;
    // B (trans, k16 x n16): row k = lane&15, n half = (lane>>4)*8
    const int b_k  = lane & 15;
    const int b_no = (lane >> 4) * 8;

    float4 a4[2];
    float4 b4[4];

    // prefetch stage 0
    {
        const float* ap = obs + (size_t)am * NTOT + k0 + 8 * aq;
        a4[0] = *(const float4*)ap;
        a4[1] = *(const float4*)(ap + 4);
        #pragma unroll
        for (int p = 0; p < 4; ++p) {
            const float* bp = W + (size_t)(k0 + wid + 8 * p) * NTOT + n0 + 4 * lane;
            b4[p] = *(const float4*)bp;
        }
    }

    float acc[2][4][4];
    #pragma unroll
    for (int mf = 0; mf < 2; ++mf)
        #pragma unroll
        for (int nf = 0; nf < 4; ++nf)
            #pragma unroll
            for (int q = 0; q < 4; ++q) acc[mf][nf][q] = 0.f;

    for (int s = 0; s < NSTAGE; ++s) {
        const int buf = s & 1;
        __syncthreads();   // previous compute on this buffer finished

        // ---- convert + STS stage s ----
        {
            char* AH = smem + OFF_AH + buf * 5120;
            char* AL = smem + OFF_AL + buf * 5120;
            unsigned h0,l0,h1,l1,h2,l2,h3,l3;
            hilo2(a4[0].x, a4[0].y, h0, l0); hilo2(a4[0].z, a4[0].w, h1, l1);
            hilo2(a4[1].x, a4[1].y, h2, l2); hilo2(a4[1].z, a4[1].w, h3, l3);
            const unsigned off = (unsigned)(am * A_STRIDE + 16 * aq);
            *(uint4*)(AH + off) = make_uint4(h0, h1, h2, h3);
            *(uint4*)(AL + off) = make_uint4(l0, l1, l2, l3);

            char* BH = smem + OFF_BH + buf * 8704;
            char* BL = smem + OFF_BL + buf * 8704;
            #pragma unroll
            for (int p = 0; p < 4; ++p) {
                unsigned bh0, bl0, bh1, bl1;
                hilo2(b4[p].x, b4[p].y, bh0, bl0);
                hilo2(b4[p].z, b4[p].w, bh1, bl1);
                const unsigned boff = (unsigned)((wid + 8 * p) * B_STRIDE + 8 * lane);
                *(uint2*)(BH + boff) = make_uint2(bh0, bh1);
                *(uint2*)(BL + boff) = make_uint2(bl0, bl1);
            }
        }

        // ---- prefetch stage s+1 (overlaps compute below) ----
        if (s + 1 < NSTAGE) {
            const int ks = k0 + (s + 1) * KSTAGE;
            const float* ap = obs + (size_t)am * NTOT + ks + 8 * aq;
            a4[0] = *(const float4*)ap;
            a4[1] = *(const float4*)(ap + 4);
            #pragma unroll
            for (int p = 0; p < 4; ++p) {
                const float* bp = W + (size_t)(ks + wid + 8 * p) * NTOT + n0 + 4 * lane;
                b4[p] = *(const float4*)bp;
            }
        }

        __syncthreads();   // STS visible

        // ---- compute stage s: 2 k16 steps ----
        const unsigned AHb = sbase + OFF_AH + buf * 5120;
        const unsigned ALb = sbase + OFF_AL + buf * 5120;
        const unsigned BHb = sbase + OFF_BH + buf * 8704;
        const unsigned BLb = sbase + OFF_BL + buf * 8704;

        #pragma unroll
        for (int kb = 0; kb < 2; ++kb) {
            unsigned ah[2][4], al[2][4];
            #pragma unroll
            for (int mf = 0; mf < 2; ++mf) {
                const unsigned aoff =
                    (unsigned)((mbase + 16 * mf + a_mo) * A_STRIDE + (kb * 16 + a_ko) * 2);
                LDMX4(ah[mf][0], ah[mf][1], ah[mf][2], ah[mf][3], AHb + aoff);
                LDMX4(al[mf][0], al[mf][1], al[mf][2], al[mf][3], ALb + aoff);
            }
            unsigned bh[4][2], bl[4][2];
            #pragma unroll
            for (int g = 0; g < 2; ++g) {   // g covers nfrags 2g, 2g+1
                const unsigned boff =
                    (unsigned)((kb * 16 + b_k) * B_STRIDE + (nbase + 16 * g + b_no) * 2);
                LDMX4T(bh[2*g][0], bh[2*g][1], bh[2*g+1][0], bh[2*g+1][1], BHb + boff);
                LDMX4T(bl[2*g][0], bl[2*g][1], bl[2*g+1][0], bl[2*g+1][1], BLb + boff);
            }
            #pragma unroll
            for (int mf = 0; mf < 2; ++mf)
                #pragma unroll
                for (int nf = 0; nf < 4; ++nf) {
                    MMA16816(acc[mf][nf], ah[mf], bh[nf]);   // Ah*Bh
                    MMA16816(acc[mf][nf], ah[mf], bl[nf]);   // Ah*Bl
                    MMA16816(acc[mf][nf], al[mf], bh[nf]);   // Al*Bh
                }
        }
    }

    // ---- epilogue: write partial to g_part[slice][m][n] ----
    float* op = g_part + (size_t)blockIdx.y * (BATCH * NTOT);
    const int r0 = lane >> 2;           // 0..7
    const int c0 = 2 * (lane & 3);      // 0,2,4,6
    #pragma unroll
    for (int mf = 0; mf < 2; ++mf)
        #pragma unroll
        for (int nf = 0; nf < 4; ++nf) {
            const int m = mbase + 16 * mf + r0;
            const int n = n0 + nbase + 8 * nf + c0;
            *(float2*)(op + (size_t)m * NTOT + n) =
                make_float2(acc[mf][nf][0], acc[mf][nf][1]);
            *(float2*)(op + (size_t)(m + 8) * NTOT + n) =
                make_float2(acc[mf][nf][2], acc[mf][nf][3]);
        }
}

// ================= Kernel B: combine + softmax + VIN + head =================
#define OFF_C     0
#define OFF_P     16384
#define OFF_RIN   20480
#define OFF_ROUT  24576
#define OFF_VA    28672
#define OFF_VB    33028
#define OFF_RED   37384
#define OFF_PATCH 37400
#define OFF_H     37436
#define OFF_IDX   37452
#define SMEMB_FLOATS 37472

__global__ __launch_bounds__(512, 1)
void vin_kernel(const float* __restrict__ obs,
                const float* __restrict__ bias,
                const float* __restrict__ w1, const float* __restrict__ b1,
                const float* __restrict__ w2, const float* __restrict__ b2,
                float* __restrict__ out)
{
    extern __shared__ float sm[];
    float* sC    = sm + OFF_C;
    float* sP    = sm + OFF_P;
    float* sRin  = sm + OFF_RIN;
    float* sRout = sm + OFF_ROUT;
    float* sVa   = sm + OFF_VA;
    float* sVb   = sm + OFF_VB;
    float* sRed  = sm + OFF_RED;
    float* sPatch= sm + OFF_PATCH;
    float* sH    = sm + OFF_H;
    int*   sIdx  = (int*)(sm + OFF_IDX);

    const int b    = blockIdx.x;
    const int tid  = threadIdx.x;
    const int lane = tid & 31;
    const int wid  = tid >> 5;

    const float* pA = g_part + (size_t)(0 * BATCH + b) * NTOT;
    const float* pB = g_part + (size_t)(1 * BATCH + b) * NTOT;
    const float* pC = g_part + (size_t)(2 * BATCH + b) * NTOT;

    for (int cell = tid; cell < 4096; cell += 512) {
        int j = cell * 3;
        sRin[cell]  = pA[j]     + pB[j]     + pC[j]     + bias[j];
        sRout[cell] = pA[j + 1] + pB[j + 1] + pC[j + 1] + bias[j + 1];
        sP[cell]    = pA[j + 2] + pB[j + 2] + pC[j + 2] + bias[j + 2];
    }
    for (int i = tid; i < 4356; i += 512) { sVa[i] = 0.f; sVb[i] = 0.f; }
    __syncthreads();

    // ---- softmax over sP (4096) ----
    float m = -INFINITY;
    #pragma unroll
    for (int r = 0; r < 8; ++r) m = fmaxf(m, sP[tid + 512 * r]);
    #pragma unroll
    for (int off = 16; off; off >>= 1)
        m = fmaxf(m, __shfl_xor_sync(0xffffffffu, m, off));
    if (lane == 0) sRed[wid] = m;
    __syncthreads();
    float gm = sRed[0];
    #pragma unroll
    for (int i = 1; i < 16; ++i) gm = fmaxf(gm, sRed[i]);
    __syncthreads();
    float s = 0.f;
    #pragma unroll
    for (int r = 0; r < 8; ++r) {
        int c = tid + 512 * r;
        float e = expf(sP[c] - gm);
        sP[c] = e; s += e;
    }
    #pragma unroll
    for (int off = 16; off; off >>= 1)
        s += __shfl_xor_sync(0xffffffffu, s, off);
    if (lane == 0) sRed[wid] = s;
    __syncthreads();
    float tot = 0.f;
    #pragma unroll
    for (int i = 0; i < 16; ++i) tot += sRed[i];
    float inv = 1.0f / tot;
    #pragma unroll
    for (int r = 0; r < 8; ++r) sP[tid + 512 * r] *= inv;

    // ---- per-direction constants: c = rin_sh - rout * (rin_sh != 0) ----
    for (int cell = tid; cell < 4096; cell += 512) {
        int h = cell >> 6, w_ = cell & 63;
        float rc = sRout[cell];
        float cu = 0.f, cd = 0.f, cl = 0.f, cr = 0.f;
        if (h > 0)   { float rn = sRin[cell - 64]; cu = rn - (rn != 0.f ? rc : 0.f); }
        if (h < 63)  { float rn = sRin[cell + 64]; cd = rn - (rn != 0.f ? rc : 0.f); }
        if (w_ > 0)  { float rn = sRin[cell - 1];  cl = rn - (rn != 0.f ? rc : 0.f); }
        if (w_ < 63) { float rn = sRin[cell + 1];  cr = rn - (rn != 0.f ? rc : 0.f); }
        sC[cell] = cu; sC[4096 + cell] = cd; sC[8192 + cell] = cl; sC[12288 + cell] = cr;
    }
    __syncthreads();

    // ---- K=64 value-iteration sweeps on padded 66x66 ping-pong V ----
    float pr[8], c0[8], c1[8], c2[8], c3[8];
    int   px[8];
    #pragma unroll
    for (int r = 0; r < 8; ++r) {
        int cell = tid + 512 * r;
        int h = cell >> 6, w_ = cell & 63;
        px[r] = (h + 1) * 66 + (w_ + 1);
        pr[r] = sP[cell];
        c0[r] = sC[cell];          c1[r] = sC[4096 + cell];
        c2[r] = sC[8192 + cell];   c3[r] = sC[12288 + cell];
    }
    float* cur = sVa;
    float* nxt = sVb;
    for (int itv = 0; itv < 64; ++itv) {
        #pragma unroll
        for (int r = 0; r < 8; ++r) {
            int pi = px[r];
            float nv = fmaf(pr[r], cur[pi - 66], c0[r]);
            nv = fmaxf(nv, fmaf(pr[r], cur[pi + 66], c1[r]));
            nv = fmaxf(nv, fmaf(pr[r], cur[pi - 1],  c2[r]));
            nv = fmaxf(nv, fmaf(pr[r], cur[pi + 1],  c3[r]));
            nxt[pi] = fmaxf(cur[pi], nv);
        }
        __syncthreads();
        float* t = cur; cur = nxt; nxt = t;
    }

    // ---- argmax of obs channel 1 (first-max semantics) ----
    const float* ob = obs + (size_t)b * NTOT;
    float bv = -INFINITY; int bi = 0;
    #pragma unroll
    for (int r = 0; r < 8; ++r) {
        int cell = tid + 512 * r;
        float v = ob[cell * 3 + 1];
        if (v > bv) { bv = v; bi = cell; }
    }
    #pragma unroll
    for (int off = 16; off; off >>= 1) {
        float ov = __shfl_down_sync(0xffffffffu, bv, off);
        int   oi = __shfl_down_sync(0xffffffffu, bi, off);
        if (ov > bv || (ov == bv && oi < bi)) { bv = ov; bi = oi; }
    }
    if (lane == 0) { sRed[wid] = bv; sIdx[wid] = bi; }
    __syncthreads();
    if (tid == 0) {
        float bb = sRed[0]; int ii = sIdx[0];
        for (int i = 1; i < 16; ++i)
            if (sRed[i] > bb || (sRed[i] == bb && sIdx[i] < ii)) { bb = sRed[i]; ii = sIdx[i]; }
        sIdx[16] = ii;
    }
    __syncthreads();
    const int am  = sIdx[16];
    const int pi_ = am >> 6, pj_ = am & 63;

    // ---- 3x3x4 patch around agent + MLP head ----
    if (tid < 36) {
        int di = tid / 12, rem = tid % 12;
        int dj = rem >> 2, ch = rem & 3;
        float v;
        if (ch == 3) {
            v = cur[(pi_ + di) * 66 + (pj_ + dj)];
        } else {
            int hh = pi_ + di - 1, ww = pj_ + dj - 1;
            v = (hh >= 0 && hh < 64 && ww >= 0 && ww < 64)
                    ? ob[(hh * 64 + ww) * 3 + ch] : 0.f;
        }
        sPatch[tid] = v;
    }
    __syncthreads();
    if (tid < 16) {
        float a = b1[tid];
        #pragma unroll
        for (int i = 0; i < 36; ++i) a = fmaf(sPatch[i], w1[i * 16 + tid], a);
        sH[tid] = fmaxf(a, 0.f);
    }
    __syncthreads();
    if (tid < 4) {
        float a = b2[tid];
        #pragma unroll
        for (int o = 0; o < 16; ++o) a = fmaf(sH[o], w2[o * 4 + tid], a);
        out[b * 4 + tid] = a;
    }
}

// ================= launcher =================
extern "C" void kernel_launch(void* const* d_in, const int* in_sizes, int n_in,
                              void* d_out, int out_size)
{
    const float* obs  = (const float*)d_in[0];
    const float* phiw = (const float*)d_in[1];
    const float* phib = (const float*)d_in[2];
    const float* w1   = (const float*)d_in[3];
    const float* b1   = (const float*)d_in[4];
    const float* w2   = (const float*)d_in[5];
    const float* b2   = (const float*)d_in[6];
    float* out = (float*)d_out;

    const int smemA = SMEMA_TOTAL;                        // 55296 B
    const int smemB = SMEMB_FLOATS * (int)sizeof(float);  // 149888 B

    cudaFuncSetAttribute(gemm_mma,   cudaFuncAttributeMaxDynamicSharedMemorySize, smemA);
    cudaFuncSetAttribute(vin_kernel, cudaFuncAttributeMaxDynamicSharedMemorySize, smemB);

    gemm_mma<<<dim3(NTOT / NTILE, NKC), 256, smemA>>>(obs, phiw);
    vin_kernel<<<BATCH, 512, smemB>>>(obs, phib, w1, b1, w2, b2, out);
}

// round 10
// speedup vs baseline: 2.6399x; 1.3998x over previous
#include <cuda_runtime.h>
#include <math.h>

// ---------------- problem constants ----------------
#define NTOT   12288         // H*W*3
#define BATCH  64
#define KCH    4096          // K per k-split slice
#define NKC    3
#define NTILE  128           // output cols per CTA
#define KSTAGE 32            // k per smem stage
#define NSTAGE (KCH / KSTAGE)   // 128

// k-split partials: [NKC][BATCH][NTOT]  (~9.4 MB scratch)
__device__ __align__(16) float g_part[NKC * BATCH * NTOT];

// ---------------- smem layout (bytes) ----------------
// AH plane: [2 buf][64 m][80 B]  (32 fp16 + pad)   per buf-plane 5120
// B planes: [2 buf][32 k][272 B] (128 fp16 + pad)  per buf-plane 8704
#define A_STRIDE 80
#define B_STRIDE 272
#define OFF_AH  0
#define OFF_BH  10240
#define OFF_BL  27648
#define SMEMA_TOTAL 45056

__device__ __forceinline__ unsigned smem_u32(const void* p) {
    unsigned a;
    asm("{ .reg .u64 t; cvta.to.shared.u64 t, %1; cvt.u32.u64 %0, t; }" : "=r"(a) : "l"(p));
    return a;
}

// pack two f32 -> f16x2 (lo = a, hi = b)
__device__ __forceinline__ unsigned packf16(float a, float b) {
    unsigned r;
    asm("cvt.rn.f16x2.f32 %0, %1, %2;" : "=r"(r) : "f"(b), "f"(a));
    return r;
}
// exact fp16 hi/lo split of a pair
__device__ __forceinline__ void hilo2h(float a, float b, unsigned& h, unsigned& l) {
    h = packf16(a, b);
    float ha, hb;
    asm("{ .reg .b16 x, y;\n\t mov.b32 {x, y}, %2;\n\t"
        "cvt.f32.f16 %0, x;\n\t cvt.f32.f16 %1, y; }"
        : "=f"(ha), "=f"(hb) : "r"(h));
    l = packf16(a - ha, b - hb);
}

#define LDMX4(r0, r1, r2, r3, addr) \
    asm volatile("ldmatrix.sync.aligned.m8n8.x4.shared.b16 {%0,%1,%2,%3}, [%4];" \
                 : "=r"(r0), "=r"(r1), "=r"(r2), "=r"(r3) : "r"(addr))
#define LDMX4T(r0, r1, r2, r3, addr) \
    asm volatile("ldmatrix.sync.aligned.m8n8.x4.trans.shared.b16 {%0,%1,%2,%3}, [%4];" \
                 : "=r"(r0), "=r"(r1), "=r"(r2), "=r"(r3) : "r"(addr))
#define MMA16816(d, a, b) \
    asm volatile("mma.sync.aligned.m16n8k16.row.col.f32.f16.f16.f32 " \
                 "{%0,%1,%2,%3}, {%4,%5,%6,%7}, {%8,%9}, {%0,%1,%2,%3};" \
                 : "+f"((d)[0]), "+f"((d)[1]), "+f"((d)[2]), "+f"((d)[3]) \
                 : "r"((a)[0]), "r"((a)[1]), "r"((a)[2]), "r"((a)[3]), \
                   "r"((b)[0]), "r"((b)[1]))

// ================= Kernel A: mma.sync fp16 2-pass GEMM =================
// C[64, 128] partial over k-chunk 4096. 8 warps = 2M x 4N, warp 32x32.
// A = fp16(obs) (rounded); W = Bh + Bl (exact split). C = Ah*Bh + Ah*Bl.
__global__ __launch_bounds__(256, 2)
void gemm_mma(const float* __restrict__ obs, const float* __restrict__ W)
{
    extern __shared__ char smem[];
    const unsigned sbase = smem_u32(smem);
    const int tid  = threadIdx.x;
    const int lane = tid & 31;
    const int wid  = tid >> 5;
    const int n0   = blockIdx.x * NTILE;
    const int k0   = blockIdx.y * KCH;

    const int wm = wid >> 2;
    const int wn = wid & 3;
    const int mbase = 32 * wm;
    const int nbase = 32 * wn;

    // loader mappings
    const int am = tid >> 2;          // A row m 0..63
    const int aq = tid & 3;           // A k-octet

    // ldmatrix lane address components
    const int a_mo = ((lane >> 3) & 1) * 8 + (lane & 7);
    const int a_ko = (lane >> 4) * 8;
    const int b_k  = lane & 15;
    const int b_no = (lane >> 4) * 8;

    float4 a4[2];
    float4 b4[4];

    // prefetch stage 0
    {
        const float* ap = obs + (size_t)am * NTOT + k0 + 8 * aq;
        a4[0] = *(const float4*)ap;
        a4[1] = *(const float4*)(ap + 4);
        #pragma unroll
        for (int p = 0; p < 4; ++p) {
            const float* bp = W + (size_t)(k0 + wid + 8 * p) * NTOT + n0 + 4 * lane;
            b4[p] = *(const float4*)bp;
        }
    }

    float acc[2][4][4];
    #pragma unroll
    for (int mf = 0; mf < 2; ++mf)
        #pragma unroll
        for (int nf = 0; nf < 4; ++nf)
            #pragma unroll
            for (int q = 0; q < 4; ++q) acc[mf][nf][q] = 0.f;

    for (int s = 0; s < NSTAGE; ++s) {
        const int buf = s & 1;
        __syncthreads();   // previous compute on this buffer finished

        // ---- convert + STS stage s ----
        {
            char* AH = smem + OFF_AH + buf * 5120;
            unsigned h0 = packf16(a4[0].x, a4[0].y);
            unsigned h1 = packf16(a4[0].z, a4[0].w);
            unsigned h2 = packf16(a4[1].x, a4[1].y);
            unsigned h3 = packf16(a4[1].z, a4[1].w);
            *(uint4*)(AH + (unsigned)(am * A_STRIDE + 16 * aq)) = make_uint4(h0, h1, h2, h3);

            char* BH = smem + OFF_BH + buf * 8704;
            char* BL = smem + OFF_BL + buf * 8704;
            #pragma unroll
            for (int p = 0; p < 4; ++p) {
                unsigned bh0, bl0, bh1, bl1;
                hilo2h(b4[p].x, b4[p].y, bh0, bl0);
                hilo2h(b4[p].z, b4[p].w, bh1, bl1);
                const unsigned boff = (unsigned)((wid + 8 * p) * B_STRIDE + 8 * lane);
                *(uint2*)(BH + boff) = make_uint2(bh0, bh1);
                *(uint2*)(BL + boff) = make_uint2(bl0, bl1);
            }
        }

        // ---- prefetch stage s+1 ----
        if (s + 1 < NSTAGE) {
            const int ks = k0 + (s + 1) * KSTAGE;
            const float* ap = obs + (size_t)am * NTOT + ks + 8 * aq;
            a4[0] = *(const float4*)ap;
            a4[1] = *(const float4*)(ap + 4);
            #pragma unroll
            for (int p = 0; p < 4; ++p) {
                const float* bp = W + (size_t)(ks + wid + 8 * p) * NTOT + n0 + 4 * lane;
                b4[p] = *(const float4*)bp;
            }
        }

        __syncthreads();   // STS visible

        // ---- compute stage s: 2 k16 steps x 2 passes ----
        const unsigned AHb = sbase + OFF_AH + buf * 5120;
        const unsigned BHb = sbase + OFF_BH + buf * 8704;
        const unsigned BLb = sbase + OFF_BL + buf * 8704;

        #pragma unroll
        for (int kb = 0; kb < 2; ++kb) {
            unsigned ah[2][4];
            #pragma unroll
            for (int mf = 0; mf < 2; ++mf) {
                const unsigned aoff =
                    (unsigned)((mbase + 16 * mf + a_mo) * A_STRIDE + (kb * 16 + a_ko) * 2);
                LDMX4(ah[mf][0], ah[mf][1], ah[mf][2], ah[mf][3], AHb + aoff);
            }
            unsigned bh[4][2], bl[4][2];
            #pragma unroll
            for (int g = 0; g < 2; ++g) {
                const unsigned boff =
                    (unsigned)((kb * 16 + b_k) * B_STRIDE + (nbase + 16 * g + b_no) * 2);
                LDMX4T(bh[2*g][0], bh[2*g][1], bh[2*g+1][0], bh[2*g+1][1], BHb + boff);
                LDMX4T(bl[2*g][0], bl[2*g][1], bl[2*g+1][0], bl[2*g+1][1], BLb + boff);
            }
            #pragma unroll
            for (int mf = 0; mf < 2; ++mf)
                #pragma unroll
                for (int nf = 0; nf < 4; ++nf) {
                    MMA16816(acc[mf][nf], ah[mf], bh[nf]);
                    MMA16816(acc[mf][nf], ah[mf], bl[nf]);
                }
        }
    }

    // ---- epilogue ----
    float* op = g_part + (size_t)blockIdx.y * (BATCH * NTOT);
    const int r0 = lane >> 2;
    const int c0 = 2 * (lane & 3);
    #pragma unroll
    for (int mf = 0; mf < 2; ++mf)
        #pragma unroll
        for (int nf = 0; nf < 4; ++nf) {
            const int m = mbase + 16 * mf + r0;
            const int n = n0 + nbase + 8 * nf + c0;
            *(float2*)(op + (size_t)m * NTOT + n) =
                make_float2(acc[mf][nf][0], acc[mf][nf][1]);
            *(float2*)(op + (size_t)(m + 8) * NTOT + n) =
                make_float2(acc[mf][nf][2], acc[mf][nf][3]);
        }
}

// ================= Kernel B: combine + softmax + VIN + head =================
// V padded grid: 66 rows x stride 68, left-pad 4: V(h,w) at (h+1)*68 + 4 + w.
#define VROW 68
#define VSZ  (66 * VROW)     // 4488
#define OFF_C     0
#define OFF_P     16384
#define OFF_RIN   20480
#define OFF_ROUT  24576
#define OFF_VA    28672
#define OFF_VB    (28672 + VSZ)
#define OFF_RED   (28672 + 2 * VSZ)
#define OFF_PATCH (OFF_RED + 16)
#define OFF_H     (OFF_PATCH + 36)
#define OFF_IDX   (OFF_H + 16)
#define SMEMB_FLOATS (OFF_IDX + 20)

__global__ __launch_bounds__(512, 1)
void vin_kernel(const float* __restrict__ obs,
                const float* __restrict__ bias,
                const float* __restrict__ w1, const float* __restrict__ b1,
                const float* __restrict__ w2, const float* __restrict__ b2,
                float* __restrict__ out)
{
    extern __shared__ float sm[];
    float* sC    = sm + OFF_C;
    float* sP    = sm + OFF_P;
    float* sRin  = sm + OFF_RIN;
    float* sRout = sm + OFF_ROUT;
    float* sVa   = sm + OFF_VA;
    float* sVb   = sm + OFF_VB;
    float* sRed  = sm + OFF_RED;
    float* sPatch= sm + OFF_PATCH;
    float* sH    = sm + OFF_H;
    int*   sIdx  = (int*)(sm + OFF_IDX);

    const int b    = blockIdx.x;
    const int tid  = threadIdx.x;
    const int lane = tid & 31;
    const int wid  = tid >> 5;

    const float* pA = g_part + (size_t)(0 * BATCH + b) * NTOT;
    const float* pB = g_part + (size_t)(1 * BATCH + b) * NTOT;
    const float* pC = g_part + (size_t)(2 * BATCH + b) * NTOT;

    for (int cell = tid; cell < 4096; cell += 512) {
        int j = cell * 3;
        sRin[cell]  = pA[j]     + pB[j]     + pC[j]     + bias[j];
        sRout[cell] = pA[j + 1] + pB[j + 1] + pC[j + 1] + bias[j + 1];
        sP[cell]    = pA[j + 2] + pB[j + 2] + pC[j + 2] + bias[j + 2];
    }
    for (int i = tid; i < VSZ; i += 512) { sVa[i] = 0.f; sVb[i] = 0.f; }
    __syncthreads();

    // ---- softmax over sP (4096) ----
    float m = -INFINITY;
    #pragma unroll
    for (int r = 0; r < 8; ++r) m = fmaxf(m, sP[tid + 512 * r]);
    #pragma unroll
    for (int off = 16; off; off >>= 1)
        m = fmaxf(m, __shfl_xor_sync(0xffffffffu, m, off));
    if (lane == 0) sRed[wid] = m;
    __syncthreads();
    float gm = sRed[0];
    #pragma unroll
    for (int i = 1; i < 16; ++i) gm = fmaxf(gm, sRed[i]);
    __syncthreads();
    float s = 0.f;
    #pragma unroll
    for (int r = 0; r < 8; ++r) {
        int c = tid + 512 * r;
        float e = expf(sP[c] - gm);
        sP[c] = e; s += e;
    }
    #pragma unroll
    for (int off = 16; off; off >>= 1)
        s += __shfl_xor_sync(0xffffffffu, s, off);
    if (lane == 0) sRed[wid] = s;
    __syncthreads();
    float tot = 0.f;
    #pragma unroll
    for (int i = 0; i < 16; ++i) tot += sRed[i];
    float inv = 1.0f / tot;
    #pragma unroll
    for (int r = 0; r < 8; ++r) sP[tid + 512 * r] *= inv;

    // ---- per-direction constants: c = rin_sh - rout * (rin_sh != 0) ----
    for (int cell = tid; cell < 4096; cell += 512) {
        int h = cell >> 6, w_ = cell & 63;
        float rc = sRout[cell];
        float cu = 0.f, cd = 0.f, cl = 0.f, cr = 0.f;
        if (h > 0)   { float rn = sRin[cell - 64]; cu = rn - (rn != 0.f ? rc : 0.f); }
        if (h < 63)  { float rn = sRin[cell + 64]; cd = rn - (rn != 0.f ? rc : 0.f); }
        if (w_ > 0)  { float rn = sRin[cell - 1];  cl = rn - (rn != 0.f ? rc : 0.f); }
        if (w_ < 63) { float rn = sRin[cell + 1];  cr = rn - (rn != 0.f ? rc : 0.f); }
        sC[cell] = cu; sC[4096 + cell] = cd; sC[8192 + cell] = cl; sC[12288 + cell] = cr;
    }
    __syncthreads();

    // ---- K=64 sweeps: 2 runs of 4 horizontally-contiguous cells per thread ----
    float pr[2][4], cU[2][4], cD[2][4], cL[2][4], cR[2][4], v[2][4];
    int   px[2];
    #pragma unroll
    for (int r = 0; r < 2; ++r) {
        const int base = 4 * (tid + 512 * r);
        const int h = base >> 6, w_ = base & 63;
        px[r] = (h + 1) * VROW + 4 + w_;
        #pragma unroll
        for (int i = 0; i < 4; ++i) {
            const int cell = base + i;
            pr[r][i] = sP[cell];
            cU[r][i] = sC[cell];          cD[r][i] = sC[4096 + cell];
            cL[r][i] = sC[8192 + cell];   cR[r][i] = sC[12288 + cell];
            v[r][i]  = 0.f;
        }
    }
    float* cur = sVa;
    float* nxt = sVb;
    for (int itv = 0; itv < 64; ++itv) {
        #pragma unroll
        for (int r = 0; r < 2; ++r) {
            const int pi = px[r];
            const float4 up = *(const float4*)(cur + pi - VROW);
            const float4 dn = *(const float4*)(cur + pi + VROW);
            const float lf  = cur[pi - 1];
            const float rt  = cur[pi + 4];
            float n0 = fmaxf(fmaxf(fmaf(pr[r][0], up.x, cU[r][0]), fmaf(pr[r][0], dn.x, cD[r][0])),
                             fmaxf(fmaf(pr[r][0], lf,      cL[r][0]), fmaf(pr[r][0], v[r][1], cR[r][0])));
            float n1 = fmaxf(fmaxf(fmaf(pr[r][1], up.y, cU[r][1]), fmaf(pr[r][1], dn.y, cD[r][1])),
                             fmaxf(fmaf(pr[r][1], v[r][0], cL[r][1]), fmaf(pr[r][1], v[r][2], cR[r][1])));
            float n2 = fmaxf(fmaxf(fmaf(pr[r][2], up.z, cU[r][2]), fmaf(pr[r][2], dn.z, cD[r][2])),
                             fmaxf(fmaf(pr[r][2], v[r][1], cL[r][2]), fmaf(pr[r][2], v[r][3], cR[r][2])));
            float n3 = fmaxf(fmaxf(fmaf(pr[r][3], up.w, cU[r][3]), fmaf(pr[r][3], dn.w, cD[r][3])),
                             fmaxf(fmaf(pr[r][3], v[r][2], cL[r][3]), fmaf(pr[r][3], rt,      cR[r][3])));
            v[r][0] = fmaxf(v[r][0], n0);
            v[r][1] = fmaxf(v[r][1], n1);
            v[r][2] = fmaxf(v[r][2], n2);
            v[r][3] = fmaxf(v[r][3], n3);
            *(float4*)(nxt + pi) = make_float4(v[r][0], v[r][1], v[r][2], v[r][3]);
        }
        __syncthreads();
        float* t = cur; cur = nxt; nxt = t;
    }
    // final V is in `cur` (even number of swaps -> sVa)

    // ---- argmax of obs channel 1 (first-max semantics) ----
    const float* ob = obs + (size_t)b * NTOT;
    float bv = -INFINITY; int bi = 0;
    #pragma unroll
    for (int r = 0; r < 8; ++r) {
        int cell = tid + 512 * r;
        float vv = ob[cell * 3 + 1];
        if (vv > bv) { bv = vv; bi = cell; }
    }
    #pragma unroll
    for (int off = 16; off; off >>= 1) {
        float ov = __shfl_down_sync(0xffffffffu, bv, off);
        int   oi = __shfl_down_sync(0xffffffffu, bi, off);
        if (ov > bv || (ov == bv && oi < bi)) { bv = ov; bi = oi; }
    }
    if (lane == 0) { sRed[wid] = bv; sIdx[wid] = bi; }
    __syncthreads();
    if (tid == 0) {
        float bb = sRed[0]; int ii = sIdx[0];
        for (int i = 1; i < 16; ++i)
            if (sRed[i] > bb || (sRed[i] == bb && sIdx[i] < ii)) { bb = sRed[i]; ii = sIdx[i]; }
        sIdx[16] = ii;
    }
    __syncthreads();
    const int am  = sIdx[16];
    const int pi_ = am >> 6, pj_ = am & 63;

    // ---- 3x3x4 patch around agent + MLP head ----
    if (tid < 36) {
        int di = tid / 12, rem = tid % 12;
        int dj = rem >> 2, ch = rem & 3;
        float vv;
        if (ch == 3) {
            vv = cur[(pi_ + di) * VROW + 3 + pj_ + dj];   // V(pi_+di-1, pj_+dj-1)
        } else {
            int hh = pi_ + di - 1, ww = pj_ + dj - 1;
            vv = (hh >= 0 && hh < 64 && ww >= 0 && ww < 64)
                    ? ob[(hh * 64 + ww) * 3 + ch] : 0.f;
        }
        sPatch[tid] = vv;
    }
    __syncthreads();
    if (tid < 16) {
        float a = b1[tid];
        #pragma unroll
        for (int i = 0; i < 36; ++i) a = fmaf(sPatch[i], w1[i * 16 + tid], a);
        sH[tid] = fmaxf(a, 0.f);
    }
    __syncthreads();
    if (tid < 4) {
        float a = b2[tid];
        #pragma unroll
        for (int o = 0; o < 16; ++o) a = fmaf(sH[o], w2[o * 4 + tid], a);
        out[b * 4 + tid] = a;
    }
}

// ================= launcher =================
extern "C" void kernel_launch(void* const* d_in, const int* in_sizes, int n_in,
                              void* d_out, int out_size)
{
    const float* obs  = (const float*)d_in[0];
    const float* phiw = (const float*)d_in[1];
    const float* phib = (const float*)d_in[2];
    const float* w1   = (const float*)d_in[3];
    const float* b1   = (const float*)d_in[4];
    const float* w2   = (const float*)d_in[5];
    const float* b2   = (const float*)d_in[6];
    float* out = (float*)d_out;

    const int smemA = SMEMA_TOTAL;                        // 45056 B
    const int smemB = SMEMB_FLOATS * (int)sizeof(float);  // ~151 KB

    cudaFuncSetAttribute(gemm_mma,   cudaFuncAttributeMaxDynamicSharedMemorySize, smemA);
    cudaFuncSetAttribute(vin_kernel, cudaFuncAttributeMaxDynamicSharedMemorySize, smemB);

    gemm_mma<<<dim3(NTOT / NTILE, NKC), 256, smemA>>>(obs, phiw);
    vin_kernel<<<BATCH, 512, smemB>>>(obs, phib, w1, b1, w2, b2, out);
}